// round 16
// baseline (speedup 1.0000x reference)
#include <cuda_runtime.h>
#include <cuda_bf16.h>

// -------- scratch: q,k,v in windowed layout [win(2048)][o(128)][n(256)] fp32 --------
__device__ float g_q[67108864];
__device__ float g_k[67108864];
__device__ float g_v[67108864];

__device__ __forceinline__ unsigned f2tf(float f) {
    unsigned u;
    asm("cvt.rna.tf32.f32 %0, %1;" : "=r"(u) : "f"(f));
    return u;
}

__device__ __forceinline__ void mma_tf32(float c[4], const unsigned a[4], const unsigned b[2]) {
    asm volatile(
        "mma.sync.aligned.m16n8k8.row.col.f32.tf32.tf32.f32 "
        "{%0,%1,%2,%3}, {%4,%5,%6,%7}, {%8,%9}, {%0,%1,%2,%3};"
        : "+f"(c[0]), "+f"(c[1]), "+f"(c[2]), "+f"(c[3])
        : "r"(a[0]), "r"(a[1]), "r"(a[2]), "r"(a[3]), "r"(b[0]), "r"(b[1]));
}

// ============================================================================
// Kernel 1: projection GEMM (tf32 tensor cores).
// grid = (3 [q,k,v], 2 [window half], 2048 [window]); block = 256 (8 warps).
// CTA tile: M=128 outputs x N=128 pixels, K=128 channels.
// Writes q/k/v directly in windowed layout so kernel 2 reads are contiguous.
// ============================================================================
__global__ __launch_bounds__(256, 2) void proj_kernel(
    const float* __restrict__ x1, const float* __restrict__ x2,
    const float* __restrict__ Wq, const float* __restrict__ Wkv)
{
    const int zt   = blockIdx.x;   // 0=q (x1,Wq), 1=k (x2,Wkv[0:128]), 2=v (x2,Wkv[128:256])
    const int half = blockIdx.y;   // window rows 0-7 or 8-15
    const int win  = blockIdx.z;   // b*256 + hi*16 + wi
    const int b  = win >> 8;
    const int hi = (win >> 4) & 15;
    const int wi = win & 15;

    const float* __restrict__ x = (zt == 0) ? x1 : x2;
    const float* __restrict__ W = (zt == 0) ? Wq : (zt == 1 ? Wkv : (Wkv + 128 * 128));
    float* __restrict__ ob = ((zt == 0) ? g_q : (zt == 1 ? g_k : g_v))
                             + (size_t)win * 32768 + half * 128;

    // strides chosen conflict-free for manual fragment loads:
    // xs bank = (k*8 + n) % 32, ws bank = (m*4 + k) % 32
    __shared__ unsigned xs[32][136];
    __shared__ unsigned ws[128][36];

    const int tid   = threadIdx.x;
    const int lane  = tid & 31;
    const int wid   = tid >> 5;
    const int warpM = wid >> 1;   // 0..3 -> 32 output rows each
    const int warpN = wid & 1;    // 0..1 -> 64 pixel cols each

    // base global index for (c=0, y=half*8, x=wi*16) of this window half
    const size_t baseX = (((size_t)b * 128 * 256) + (size_t)(hi * 16 + half * 8)) * 256 + wi * 16;

    float acc[2][8][4];
    #pragma unroll
    for (int i = 0; i < 2; i++)
        #pragma unroll
        for (int j = 0; j < 8; j++)
            #pragma unroll
            for (int r = 0; r < 4; r++) acc[i][j][r] = 0.f;

    for (int kc = 0; kc < 128; kc += 32) {
        // ---- load x tile: 32 channels x 128 pixels (8 rows x 16 cols), float4 ----
        #pragma unroll
        for (int j = 0; j < 4; j++) {
            int li  = tid + j * 256;          // 0..1023 float4 slots
            int c   = li >> 5;                // channel within K tile
            int rem = li & 31;
            int yy  = rem >> 2;               // row within half (0..7)
            int x4  = rem & 3;                // float4 within row
            float4 v = *reinterpret_cast<const float4*>(
                x + baseX + (size_t)(kc + c) * 65536 + (size_t)yy * 256 + x4 * 4);
            int p = yy * 16 + x4 * 4;         // pixel index within half
            xs[c][p + 0] = f2tf(v.x); xs[c][p + 1] = f2tf(v.y);
            xs[c][p + 2] = f2tf(v.z); xs[c][p + 3] = f2tf(v.w);
        }
        // ---- load W tile: 128 rows x 32 k, float4 ----
        #pragma unroll
        for (int j = 0; j < 4; j++) {
            int li = tid + j * 256;
            int m  = li >> 3;
            int k4 = li & 7;
            float4 v = *reinterpret_cast<const float4*>(W + m * 128 + kc + k4 * 4);
            ws[m][k4 * 4 + 0] = f2tf(v.x); ws[m][k4 * 4 + 1] = f2tf(v.y);
            ws[m][k4 * 4 + 2] = f2tf(v.z); ws[m][k4 * 4 + 3] = f2tf(v.w);
        }
        __syncthreads();

        #pragma unroll
        for (int ki = 0; ki < 32; ki += 8) {
            const int klo = ki + (lane & 3);
            unsigned afr[2][4];
            #pragma unroll
            for (int mt = 0; mt < 2; mt++) {
                int m = warpM * 32 + mt * 16 + (lane >> 2);
                afr[mt][0] = ws[m][klo];
                afr[mt][1] = ws[m + 8][klo];
                afr[mt][2] = ws[m][klo + 4];
                afr[mt][3] = ws[m + 8][klo + 4];
            }
            #pragma unroll
            for (int nt = 0; nt < 8; nt++) {
                unsigned bfr[2];
                int n = warpN * 64 + nt * 8 + (lane >> 2);
                bfr[0] = xs[klo][n];
                bfr[1] = xs[klo + 4][n];
                mma_tf32(acc[0][nt], afr[0], bfr);
                mma_tf32(acc[1][nt], afr[1], bfr);
            }
        }
        __syncthreads();
    }

    // ---- epilogue: fragment (row,col) -> scratch [win][o][half*128 + col] ----
    #pragma unroll
    for (int mt = 0; mt < 2; mt++) {
        int m0 = warpM * 32 + mt * 16 + (lane >> 2);
        #pragma unroll
        for (int nt = 0; nt < 8; nt++) {
            int col = warpN * 64 + nt * 8 + 2 * (lane & 3);
            *reinterpret_cast<float2*>(ob + (size_t)m0 * 256 + col) =
                make_float2(acc[mt][nt][0], acc[mt][nt][1]);
            *reinterpret_cast<float2*>(ob + (size_t)(m0 + 8) * 256 + col) =
                make_float2(acc[mt][nt][2], acc[mt][nt][3]);
        }
    }
}

// ============================================================================
// Kernel 2: windowed linear attention, fp32.
// grid = 16384 (window-head), block = 256 (thread n = token).
// ============================================================================
__global__ __launch_bounds__(256) void attn_kernel(float* __restrict__ out)
{
    const int wh  = blockIdx.x;      // win*8 + h
    const int win = wh >> 3;
    const int h   = wh & 7;
    const int b   = win >> 8;
    const int hi  = (win >> 4) & 15;
    const int wi  = win & 15;

    __shared__ float sk[16][256];    // normalized k
    __shared__ float sv[16][256];    // raw v
    __shared__ float kvacc[16][16];  // [m][c]
    __shared__ float ksum[16];
    __shared__ float vsum[16];

    const int tid = threadIdx.x;     // token n
    if (tid < 16) { ksum[tid] = 0.f; vsum[tid] = 0.f; }

    const float* __restrict__ qb = g_q + (size_t)wh * 4096;
    const float* __restrict__ kb = g_k + (size_t)wh * 4096;
    const float* __restrict__ vb = g_v + (size_t)wh * 4096;

    float qn[16], kn[16], vn[16];
    float sq = 0.f, sks = 0.f;
    #pragma unroll
    for (int d = 0; d < 16; d++) {
        qn[d] = qb[d * 256 + tid]; sq  += qn[d] * qn[d];
        kn[d] = kb[d * 256 + tid]; sks += kn[d] * kn[d];
        vn[d] = vb[d * 256 + tid];
    }
    const float rq = rsqrtf(sq);
    const float rk = rsqrtf(sks);
    #pragma unroll
    for (int d = 0; d < 16; d++) {
        qn[d] *= rq;
        kn[d] *= rk;
        sk[d][tid] = kn[d];
        sv[d][tid] = vn[d];
    }
    __syncthreads();

    // ksum[d] = sum_n kn[d][n]; vsum[d] = sum_n v[d][n]  (warp shuffle + atomic)
    #pragma unroll
    for (int d = 0; d < 16; d++) {
        float kv = kn[d], vv = vn[d];
        #pragma unroll
        for (int off = 16; off; off >>= 1) {
            kv += __shfl_xor_sync(0xffffffffu, kv, off);
            vv += __shfl_xor_sync(0xffffffffu, vv, off);
        }
        if ((tid & 31) == 0) {
            atomicAdd(&ksum[d], kv);
            atomicAdd(&vsum[d], vv);
        }
    }

    // kv_acc[m][c] = sum_n kn[m][n] * v[c][n]  (one thread per (m,c))
    {
        const int m = tid >> 4, c = tid & 15;
        const float4* krow = reinterpret_cast<const float4*>(&sk[m][0]);
        const float4* vrow = reinterpret_cast<const float4*>(&sv[c][0]);
        float a = 0.f;
        #pragma unroll 8
        for (int n = 0; n < 64; n++) {
            float4 k4 = krow[n], v4 = vrow[n];
            a += k4.x * v4.x + k4.y * v4.y + k4.z * v4.z + k4.w * v4.w;
        }
        kvacc[m][c] = a;
    }
    __syncthreads();

    // tailor + output for token tid
    float denom = 256.f;
    #pragma unroll
    for (int d = 0; d < 16; d++) denom += qn[d] * (ksum[d] + 1e-6f);
    const float t = 1.0f / denom;

    float oc[16];
    #pragma unroll
    for (int c = 0; c < 16; c++) oc[c] = vsum[c];
    #pragma unroll
    for (int m = 0; m < 16; m++) {
        const float qm = qn[m];
        #pragma unroll
        for (int c = 0; c < 16; c++) oc[c] += qm * kvacc[m][c];
    }

    // out[b][h*16+c][hi*16 + y][wi*16 + x], y = tid>>4, x = tid&15
    const size_t obase =
        ((((size_t)b * 128 + h * 16) * 256) + (size_t)(hi * 16 + (tid >> 4))) * 256
        + wi * 16 + (tid & 15);
    #pragma unroll
    for (int c = 0; c < 16; c++) out[obase + (size_t)c * 65536] = oc[c] * t;
}

// ============================================================================
extern "C" void kernel_launch(void* const* d_in, const int* in_sizes, int n_in,
                              void* d_out, int out_size)
{
    const float* x1  = (const float*)d_in[0];
    const float* x2  = (const float*)d_in[1];
    const float* Wq  = (const float*)d_in[2];
    const float* Wkv = (const float*)d_in[3];
    float* out = (float*)d_out;

    dim3 g1(3, 2, 2048);   // z-fastest over (q,k,v) so x2 tiles hit L2 twice
    proj_kernel<<<g1, 256>>>(x1, x2, Wq, Wkv);
    attn_kernel<<<16384, 256>>>(out);
}

// round 17
// speedup vs baseline: 1.8342x; 1.8342x over previous
#include <cuda_runtime.h>
#include <cuda_bf16.h>

// -------- scratch: q,k,v in windowed layout [win(2048)][o(128)][n(256)] fp32 --------
__device__ float g_q[67108864];
__device__ float g_k[67108864];
__device__ float g_v[67108864];

__device__ __forceinline__ unsigned f2tf(float f) {
    unsigned u;
    asm("cvt.rna.tf32.f32 %0, %1;" : "=r"(u) : "f"(f));
    return u;
}

__device__ __forceinline__ void mma_tf32(float c[4], const unsigned a[4], const unsigned b[2]) {
    asm volatile(
        "mma.sync.aligned.m16n8k8.row.col.f32.tf32.tf32.f32 "
        "{%0,%1,%2,%3}, {%4,%5,%6,%7}, {%8,%9}, {%0,%1,%2,%3};"
        : "+f"(c[0]), "+f"(c[1]), "+f"(c[2]), "+f"(c[3])
        : "r"(a[0]), "r"(a[1]), "r"(a[2]), "r"(a[3]), "r"(b[0]), "r"(b[1]));
}

// ============================================================================
// Kernel 1: projection GEMM (tf32 tensor cores).  (unchanged this round)
// grid = (3 [q,k,v], 2 [window half], 2048 [window]); block = 256 (8 warps).
// CTA tile: M=128 outputs x N=128 pixels, K=128 channels.
// ============================================================================
__global__ __launch_bounds__(256, 2) void proj_kernel(
    const float* __restrict__ x1, const float* __restrict__ x2,
    const float* __restrict__ Wq, const float* __restrict__ Wkv)
{
    const int zt   = blockIdx.x;   // 0=q (x1,Wq), 1=k (x2,Wkv[0:128]), 2=v (x2,Wkv[128:256])
    const int half = blockIdx.y;   // window rows 0-7 or 8-15
    const int win  = blockIdx.z;   // b*256 + hi*16 + wi
    const int b  = win >> 8;
    const int hi = (win >> 4) & 15;
    const int wi = win & 15;

    const float* __restrict__ x = (zt == 0) ? x1 : x2;
    const float* __restrict__ W = (zt == 0) ? Wq : (zt == 1 ? Wkv : (Wkv + 128 * 128));
    float* __restrict__ ob = ((zt == 0) ? g_q : (zt == 1 ? g_k : g_v))
                             + (size_t)win * 32768 + half * 128;

    __shared__ unsigned xs[32][136];
    __shared__ unsigned ws[128][36];

    const int tid   = threadIdx.x;
    const int lane  = tid & 31;
    const int wid   = tid >> 5;
    const int warpM = wid >> 1;
    const int warpN = wid & 1;

    const size_t baseX = (((size_t)b * 128 * 256) + (size_t)(hi * 16 + half * 8)) * 256 + wi * 16;

    float acc[2][8][4];
    #pragma unroll
    for (int i = 0; i < 2; i++)
        #pragma unroll
        for (int j = 0; j < 8; j++)
            #pragma unroll
            for (int r = 0; r < 4; r++) acc[i][j][r] = 0.f;

    for (int kc = 0; kc < 128; kc += 32) {
        #pragma unroll
        for (int j = 0; j < 4; j++) {
            int li  = tid + j * 256;
            int c   = li >> 5;
            int rem = li & 31;
            int yy  = rem >> 2;
            int x4  = rem & 3;
            float4 v = *reinterpret_cast<const float4*>(
                x + baseX + (size_t)(kc + c) * 65536 + (size_t)yy * 256 + x4 * 4);
            int p = yy * 16 + x4 * 4;
            xs[c][p + 0] = f2tf(v.x); xs[c][p + 1] = f2tf(v.y);
            xs[c][p + 2] = f2tf(v.z); xs[c][p + 3] = f2tf(v.w);
        }
        #pragma unroll
        for (int j = 0; j < 4; j++) {
            int li = tid + j * 256;
            int m  = li >> 3;
            int k4 = li & 7;
            float4 v = *reinterpret_cast<const float4*>(W + m * 128 + kc + k4 * 4);
            ws[m][k4 * 4 + 0] = f2tf(v.x); ws[m][k4 * 4 + 1] = f2tf(v.y);
            ws[m][k4 * 4 + 2] = f2tf(v.z); ws[m][k4 * 4 + 3] = f2tf(v.w);
        }
        __syncthreads();

        #pragma unroll
        for (int ki = 0; ki < 32; ki += 8) {
            const int klo = ki + (lane & 3);
            unsigned afr[2][4];
            #pragma unroll
            for (int mt = 0; mt < 2; mt++) {
                int m = warpM * 32 + mt * 16 + (lane >> 2);
                afr[mt][0] = ws[m][klo];
                afr[mt][1] = ws[m + 8][klo];
                afr[mt][2] = ws[m][klo + 4];
                afr[mt][3] = ws[m + 8][klo + 4];
            }
            #pragma unroll
            for (int nt = 0; nt < 8; nt++) {
                unsigned bfr[2];
                int n = warpN * 64 + nt * 8 + (lane >> 2);
                bfr[0] = xs[klo][n];
                bfr[1] = xs[klo + 4][n];
                mma_tf32(acc[0][nt], afr[0], bfr);
                mma_tf32(acc[1][nt], afr[1], bfr);
            }
        }
        __syncthreads();
    }

    #pragma unroll
    for (int mt = 0; mt < 2; mt++) {
        int m0 = warpM * 32 + mt * 16 + (lane >> 2);
        #pragma unroll
        for (int nt = 0; nt < 8; nt++) {
            int col = warpN * 64 + nt * 8 + 2 * (lane & 3);
            *reinterpret_cast<float2*>(ob + (size_t)m0 * 256 + col) =
                make_float2(acc[mt][nt][0], acc[mt][nt][1]);
            *reinterpret_cast<float2*>(ob + (size_t)(m0 + 8) * 256 + col) =
                make_float2(acc[mt][nt][2], acc[mt][nt][3]);
        }
    }
}

// ============================================================================
// Kernel 2: windowed linear attention, fp32.
// grid = 16384 (window-head), block = 256 (thread n = token).
// Round-16 change: pad sk/sv rows to 260 words (1040 B, 16B-aligned,
// 260 mod 32 = 4) so the kv_acc float4 reads of 16 distinct rows land on
// distinct bank groups (2 phases = BW floor, was 16-way conflict), and
// read kvacc in the epilogue as broadcast float4 (64 LDS.128 vs 256 LDS.32).
// ============================================================================
__global__ __launch_bounds__(256) void attn_kernel(float* __restrict__ out)
{
    const int wh  = blockIdx.x;      // win*8 + h
    const int win = wh >> 3;
    const int h   = wh & 7;
    const int b   = win >> 8;
    const int hi  = (win >> 4) & 15;
    const int wi  = win & 15;

    __shared__ float sk[16][260];    // normalized k  (padded: bank group 4*row)
    __shared__ float sv[16][260];    // raw v         (padded)
    __shared__ float kvacc[16][16];  // [m][c]
    __shared__ float ksum[16];
    __shared__ float vsum[16];

    const int tid = threadIdx.x;     // token n
    if (tid < 16) { ksum[tid] = 0.f; vsum[tid] = 0.f; }

    const float* __restrict__ qb = g_q + (size_t)wh * 4096;
    const float* __restrict__ kb = g_k + (size_t)wh * 4096;
    const float* __restrict__ vb = g_v + (size_t)wh * 4096;

    float qn[16], kn[16], vn[16];
    float sq = 0.f, sks = 0.f;
    #pragma unroll
    for (int d = 0; d < 16; d++) {
        qn[d] = qb[d * 256 + tid]; sq  += qn[d] * qn[d];
        kn[d] = kb[d * 256 + tid]; sks += kn[d] * kn[d];
        vn[d] = vb[d * 256 + tid];
    }
    const float rq = rsqrtf(sq);
    const float rk = rsqrtf(sks);
    #pragma unroll
    for (int d = 0; d < 16; d++) {
        qn[d] *= rq;
        kn[d] *= rk;
        sk[d][tid] = kn[d];
        sv[d][tid] = vn[d];
    }
    __syncthreads();

    // ksum[d] = sum_n kn[d][n]; vsum[d] = sum_n v[d][n]  (warp shuffle + atomic)
    #pragma unroll
    for (int d = 0; d < 16; d++) {
        float kv = kn[d], vv = vn[d];
        #pragma unroll
        for (int off = 16; off; off >>= 1) {
            kv += __shfl_xor_sync(0xffffffffu, kv, off);
            vv += __shfl_xor_sync(0xffffffffu, vv, off);
        }
        if ((tid & 31) == 0) {
            atomicAdd(&ksum[d], kv);
            atomicAdd(&vsum[d], vv);
        }
    }

    // kv_acc[m][c] = sum_n kn[m][n] * v[c][n]  (one thread per (m,c))
    // krow: broadcast within 16-thread group, rows m/m+? on distinct banks.
    // vrow: 16 distinct rows -> bank groups 4c mod 32 -> 2 conflict-free phases.
    {
        const int m = tid >> 4, c = tid & 15;
        const float4* krow = reinterpret_cast<const float4*>(&sk[m][0]);
        const float4* vrow = reinterpret_cast<const float4*>(&sv[c][0]);
        float a = 0.f;
        #pragma unroll 8
        for (int n = 0; n < 64; n++) {
            float4 k4 = krow[n], v4 = vrow[n];
            a += k4.x * v4.x + k4.y * v4.y + k4.z * v4.z + k4.w * v4.w;
        }
        kvacc[m][c] = a;
    }
    __syncthreads();

    // tailor + output for token tid
    float denom = 256.f;
    #pragma unroll
    for (int d = 0; d < 16; d++) denom += qn[d] * (ksum[d] + 1e-6f);
    const float t = 1.0f / denom;

    float oc[16];
    #pragma unroll
    for (int c = 0; c < 16; c++) oc[c] = vsum[c];

    const float4* kvr = reinterpret_cast<const float4*>(&kvacc[0][0]);
    #pragma unroll
    for (int m = 0; m < 16; m++) {
        const float qm = qn[m];
        #pragma unroll
        for (int j = 0; j < 4; j++) {
            float4 k4 = kvr[m * 4 + j];       // broadcast LDS.128
            oc[j * 4 + 0] += qm * k4.x;
            oc[j * 4 + 1] += qm * k4.y;
            oc[j * 4 + 2] += qm * k4.z;
            oc[j * 4 + 3] += qm * k4.w;
        }
    }

    // out[b][h*16+c][hi*16 + y][wi*16 + x], y = tid>>4, x = tid&15
    const size_t obase =
        ((((size_t)b * 128 + h * 16) * 256) + (size_t)(hi * 16 + (tid >> 4))) * 256
        + wi * 16 + (tid & 15);
    #pragma unroll
    for (int c = 0; c < 16; c++) out[obase + (size_t)c * 65536] = oc[c] * t;
}

// ============================================================================
extern "C" void kernel_launch(void* const* d_in, const int* in_sizes, int n_in,
                              void* d_out, int out_size)
{
    const float* x1  = (const float*)d_in[0];
    const float* x2  = (const float*)d_in[1];
    const float* Wq  = (const float*)d_in[2];
    const float* Wkv = (const float*)d_in[3];
    float* out = (float*)d_out;

    dim3 g1(3, 2, 2048);   // x-fastest over (q,k,v) so x2 tiles hit L2 twice
    proj_kernel<<<g1, 256>>>(x1, x2, Wq, Wkv);
    attn_kernel<<<16384, 256>>>(out);
}